// round 9
// baseline (speedup 1.0000x reference)
#include <cuda_runtime.h>
#include <math.h>
#include <stdint.h>

#define BB 32
#define NN 3136
#define DD 384
#define HH 8
#define CC 48
#define BH 256          // BB*HH
#define ROWS 100352     // BB*NN
#define E3 1152         // 3*DD
#define NSPLIT 7
#define NCHUNK 448      // NN / NSPLIT

// Scratch (sanctioned __device__ globals; no allocations anywhere)
__device__ float g_qkv[(size_t)3 * BH * CC * NN];   // [3][bh][c][n]; v tf32-rounded
__device__ float g_xc[(size_t)ROWS * DD];           // tf32-rounded x, k-pair-permuted
__device__ float g_wc[(size_t)E3 * DD];             // tf32-rounded qkv_w, k-pair-permuted
__device__ float g_npart[(size_t)NSPLIT * BH * 96]; // sumsq partials (q rows, k rows)
__device__ float g_spart[(size_t)NSPLIT * BH * CC * CC];
__device__ float g_p[(size_t)BH * CC * CC];         // softmaxed attn
__device__ float g_w2[(size_t)BB * DD * DD];        // fused P@W weights, tf32-rounded

// ---------------------------------------------------------------------------
// helpers
// ---------------------------------------------------------------------------
__device__ __forceinline__ uint32_t smem_u32(const void* p) {
    uint32_t a;
    asm("{ .reg .u64 t; cvta.to.shared.u64 t, %1; cvt.u32.u64 %0, t; }"
        : "=r"(a) : "l"(p));
    return a;
}
__device__ __forceinline__ unsigned cvtu(float f) {   // fp32 -> tf32 bits (rna)
    unsigned r;
    asm("cvt.rna.tf32.f32 %0, %1;" : "=r"(r) : "f"(f));
    return r;
}
__device__ __forceinline__ void mma_tf32(float* c, const unsigned* a,
                                         const unsigned* b) {
    asm volatile(
        "mma.sync.aligned.m16n8k8.row.col.f32.tf32.tf32.f32 "
        "{%0,%1,%2,%3}, {%4,%5,%6,%7}, {%8,%9}, {%0,%1,%2,%3};\n"
        : "+f"(c[0]), "+f"(c[1]), "+f"(c[2]), "+f"(c[3])
        : "r"(a[0]), "r"(a[1]), "r"(a[2]), "r"(a[3]), "r"(b[0]), "r"(b[1]));
}
__device__ __forceinline__ void cpa16(uint32_t s, const float* g) {
    asm volatile("cp.async.ca.shared.global [%0], [%1], 16;"
                 :: "r"(s), "l"(g) : "memory");
}
#define CPA_COMMIT() asm volatile("cp.async.commit_group;" ::: "memory")
#define CPA_WAIT1()  asm volatile("cp.async.wait_group 1;" ::: "memory")
#define CPA_WAIT0()  asm volatile("cp.async.wait_group 0;" ::: "memory")
#define FU(x) __float_as_uint(x)

// ---------------------------------------------------------------------------
// K0: pre-round x and qkv_w to tf32 AND permute k-columns within each 8-group
// to [0,4,1,5,2,6,3,7] so tf32 fragment pairs (tg, tg+4) become adjacent.
// ---------------------------------------------------------------------------
__global__ __launch_bounds__(256) void k_cvt(const float* __restrict__ x,
                                             const float* __restrict__ w) {
    const size_t NX4 = (size_t)ROWS * DD / 4;
    const size_t NW4 = (size_t)E3 * DD / 4;
    for (size_t i = (size_t)blockIdx.x * 256 + threadIdx.x; i < NX4 + NW4;
         i += (size_t)gridDim.x * 256) {
        const float4 v = (i < NX4) ? ((const float4*)x)[i]
                                   : ((const float4*)w)[i - NX4];
        float* dst = (i < NX4) ? g_xc : g_wc;
        size_t e0 = (i < NX4 ? i : i - NX4) * 4;       // first element index
        // 4 consecutive k share an 8-group; odd half (k&4) goes to odd slots
        size_t base = (e0 & ~(size_t)7) + ((e0 & 4) ? 1 : 0) +
                      (e0 / DD) * 0;                   // e0 already flat
        dst[base + 0] = __uint_as_float(cvtu(v.x));
        dst[base + 2] = __uint_as_float(cvtu(v.y));
        dst[base + 4] = __uint_as_float(cvtu(v.z));
        dst[base + 6] = __uint_as_float(cvtu(v.w));
    }
}

// ---------------------------------------------------------------------------
// K1: qkv = xc @ wc^T via tf32 MMA + cp.async double buffering.
// Inputs pre-rounded + k-pair-permuted -> fragment loads are LDS.64.
// 128x128 tile, 12 K-chunks of 32; rows padded to 40 floats (conflict-free).
// ---------------------------------------------------------------------------
__global__ __launch_bounds__(256) void k_qkv() {
    extern __shared__ float ds[];
    float (*As)[128][40] = (float (*)[128][40])ds;
    float (*Bs)[128][40] = (float (*)[128][40])(ds + 2 * 128 * 40);
    const int m0 = blockIdx.y * 128, e0 = blockIdx.x * 128;
    const int t = threadIdx.x, lane = t & 31, wid = t >> 5;
    const int wm = wid >> 2, wn = wid & 3;
    const int g = lane >> 2, tg = lane & 3;
    const int lr = t >> 3, ls = (t & 7) * 4;

    const float* gx = g_xc + (size_t)(m0 + lr) * DD + ls;
    const float* gw = g_wc + (size_t)(e0 + lr) * DD + ls;

    float acc[16][4];
#pragma unroll
    for (int i = 0; i < 16; i++)
#pragma unroll
        for (int j = 0; j < 4; j++) acc[i][j] = 0.f;

#define ISSUE_QKV(buf, k0)                                                   \
    do {                                                                     \
        _Pragma("unroll")                                                    \
        for (int i = 0; i < 4; i++) {                                        \
            cpa16(smem_u32(&As[buf][lr + 32 * i][ls]),                       \
                  gx + (size_t)(32 * i) * DD + (k0));                        \
            cpa16(smem_u32(&Bs[buf][lr + 32 * i][ls]),                       \
                  gw + (size_t)(32 * i) * DD + (k0));                        \
        }                                                                    \
    } while (0)

    ISSUE_QKV(0, 0);
    CPA_COMMIT();

    for (int ch = 0; ch < 12; ch++) {
        const int buf = ch & 1;
        if (ch < 11) {
            ISSUE_QKV(buf ^ 1, (ch + 1) * 32);
            CPA_COMMIT();
            CPA_WAIT1();
        } else {
            CPA_WAIT0();
        }
        __syncthreads();
#pragma unroll
        for (int kk = 0; kk < 4; kk++) {
            unsigned a[4][4], b[4][2];
            const int kc = kk * 8 + 2 * tg;   // physical col of (tg, tg+4) pair
#pragma unroll
            for (int mi = 0; mi < 4; mi++) {
                int m = wm * 64 + mi * 16 + g;
                float2 lo = *(const float2*)&As[buf][m][kc];
                float2 hi = *(const float2*)&As[buf][m + 8][kc];
                a[mi][0] = FU(lo.x); a[mi][2] = FU(lo.y);
                a[mi][1] = FU(hi.x); a[mi][3] = FU(hi.y);
            }
#pragma unroll
            for (int ni = 0; ni < 4; ni++) {
                int e = wn * 32 + ni * 8 + g;
                float2 bb = *(const float2*)&Bs[buf][e][kc];
                b[ni][0] = FU(bb.x); b[ni][1] = FU(bb.y);
            }
#pragma unroll
            for (int mi = 0; mi < 4; mi++)
#pragma unroll
                for (int ni = 0; ni < 4; ni++)
                    mma_tf32(acc[mi * 4 + ni], a[mi], b[ni]);
        }
        __syncthreads();
    }
#undef ISSUE_QKV

    // Epilogue: stage [eL][m] slabs in smem, stream n-contiguous scatter;
    // v (s==2) rounded to tf32 so k_proj can skip cvt.
    float (*Cs)[132] = (float (*)[132])ds;   // 32 x 132
#pragma unroll 1
    for (int slab = 0; slab < 4; slab++) {
        if (wn == slab) {
#pragma unroll
            for (int mi = 0; mi < 4; mi++)
#pragma unroll
                for (int ni = 0; ni < 4; ni++) {
                    int eL = ni * 8 + 2 * tg;
                    int m = wm * 64 + mi * 16 + g;
                    float* a4 = acc[mi * 4 + ni];
                    Cs[eL][m]         = a4[0];
                    Cs[eL + 1][m]     = a4[1];
                    Cs[eL][m + 8]     = a4[2];
                    Cs[eL + 1][m + 8] = a4[3];
                }
        }
        __syncthreads();
#pragma unroll
        for (int it = 0; it < 4; it++) {
            int idx = t + 256 * it;          // 0..1023
            int eL = idx >> 5, f = idx & 31;
            int e = e0 + slab * 32 + eL;
            int s = e / DD;
            int rem = e - s * DD;
            int h = rem / CC;
            int c = rem - h * CC;
            int m = m0 + 4 * f;
            int b_ = m / NN;
            int n = m - b_ * NN;
            float4 vv = *(float4*)&Cs[eL][4 * f];
            if (s == 2) {
                vv.x = __uint_as_float(cvtu(vv.x));
                vv.y = __uint_as_float(cvtu(vv.y));
                vv.z = __uint_as_float(cvtu(vv.z));
                vv.w = __uint_as_float(cvtu(vv.w));
            }
            *(float4*)(g_qkv + ((size_t)((s * BB + b_) * HH + h) * CC + c) * NN + n) = vv;
        }
        __syncthreads();
    }
}

// ---------------------------------------------------------------------------
// K3a: partial S[c][d] = sum_n q[c][n] k[d][n] over an n-chunk
//      + fused per-row sumsq partials (threads 0..95)
// ---------------------------------------------------------------------------
__global__ __launch_bounds__(256) void k_qk() {
    __shared__ float qs[48][68];
    __shared__ float ks[48][68];
    const int bh = blockIdx.x;
    const int n0 = blockIdx.y * NCHUNK;
    const int t  = threadIdx.x;
    const int ci = t >> 4, dj = t & 15;

    const float* qb = g_qkv + (size_t)bh * CC * NN;
    const float* kb = g_qkv + (size_t)(BH + bh) * CC * NN;

    float acc[3][3] = {};
    float nacc = 0.f;
    for (int cc = 0; cc < NCHUNK; cc += 64) {
        int nb = n0 + cc;
#pragma unroll
        for (int jj = 0; jj < 3; jj++) {
            int idx = t + 256 * jj;
            int c = idx >> 4, f = idx & 15;
            *(float4*)&qs[c][4 * f] = *(const float4*)(qb + (size_t)c * NN + nb + 4 * f);
            *(float4*)&ks[c][4 * f] = *(const float4*)(kb + (size_t)c * NN + nb + 4 * f);
        }
        __syncthreads();
        if (t < 96) {
            const float4* rowp = (t < 48) ? (const float4*)&qs[t][0]
                                          : (const float4*)&ks[t - 48][0];
#pragma unroll
            for (int f = 0; f < 16; f++) {
                float4 v = rowp[f];
                nacc += v.x * v.x + v.y * v.y + v.z * v.z + v.w * v.w;
            }
        }
#pragma unroll 8
        for (int nn = 0; nn < 64; nn++) {
            float a0 = qs[3 * ci + 0][nn];
            float a1 = qs[3 * ci + 1][nn];
            float a2 = qs[3 * ci + 2][nn];
            float b0 = ks[3 * dj + 0][nn];
            float b1 = ks[3 * dj + 1][nn];
            float b2 = ks[3 * dj + 2][nn];
            acc[0][0] += a0 * b0; acc[0][1] += a0 * b1; acc[0][2] += a0 * b2;
            acc[1][0] += a1 * b0; acc[1][1] += a1 * b1; acc[1][2] += a1 * b2;
            acc[2][0] += a2 * b0; acc[2][1] += a2 * b1; acc[2][2] += a2 * b2;
        }
        __syncthreads();
    }
    float* out = g_spart + ((size_t)blockIdx.y * BH + bh) * (CC * CC);
#pragma unroll
    for (int i = 0; i < 3; i++)
#pragma unroll
        for (int j = 0; j < 3; j++)
            out[(3 * ci + i) * CC + (3 * dj + j)] = acc[i][j];
    if (t < 96)
        g_npart[((size_t)blockIdx.y * BH + bh) * 96 + t] = nacc;
}

// ---------------------------------------------------------------------------
// K3b: reduce partials (S and norms), scale, row softmax -> g_p
// ---------------------------------------------------------------------------
__global__ __launch_bounds__(64) void k_softmax(const float* __restrict__ temp) {
    __shared__ float S[48][48];
    __shared__ float inorm[96];
    const int bh = blockIdx.x;
    const int t  = threadIdx.x;
    const float tp = temp[bh % HH];
    for (int r = t; r < 96; r += 64) {
        float s = 0.f;
#pragma unroll
        for (int p = 0; p < NSPLIT; p++)
            s += g_npart[((size_t)p * BH + bh) * 96 + r];
        inorm[r] = 1.f / fmaxf(sqrtf(s), 1e-12f);
    }
    __syncthreads();
    for (int idx = t; idx < CC * CC; idx += 64) {
        float s = 0.f;
#pragma unroll
        for (int p = 0; p < NSPLIT; p++)
            s += g_spart[((size_t)p * BH + bh) * (CC * CC) + idx];
        int c = idx / CC, d = idx - c * CC;
        s *= inorm[c] * inorm[48 + d] * tp;
        S[c][d] = s;
    }
    __syncthreads();
    if (t < 48) {
        float mx = -1e30f;
#pragma unroll
        for (int d = 0; d < 48; d++) mx = fmaxf(mx, S[t][d]);
        float sum = 0.f;
#pragma unroll
        for (int d = 0; d < 48; d++) {
            float e = __expf(S[t][d] - mx);
            S[t][d] = e;
            sum += e;
        }
        float inv = 1.f / sum;
#pragma unroll
        for (int d = 0; d < 48; d++)
            g_p[(size_t)bh * (CC * CC) + t * CC + d] = S[t][d] * inv;
    }
}

// ---------------------------------------------------------------------------
// K_W2: W2[b][e][h*48+d] = sum_c P[b,h,c,d] * W[e][h*48+c]  (tf32-rounded out)
// grid (BH, 3); 4 independent c-partials per output for ILP
// ---------------------------------------------------------------------------
__global__ __launch_bounds__(256) void k_wprime(const float* __restrict__ w) {
    __shared__ float Ps[48][49];   // [c][d]
    const int bh = blockIdx.x;
    const int b_ = bh / HH, h = bh % HH;
    const int eseg = blockIdx.y;   // 0..2, 128 e each
    const int t = threadIdx.x;
    for (int idx = t; idx < CC * CC; idx += 256) {
        int c = idx / CC;
        Ps[c][idx - c * CC] = g_p[(size_t)bh * (CC * CC) + idx];
    }
    __syncthreads();
    // 128 e x 48 d outputs; idx = eL*48 + d
    for (int idx = t; idx < 128 * CC; idx += 256) {
        int eL = idx / CC, d = idx - (idx / CC) * CC;
        int e = eseg * 128 + eL;
        const float* wr = w + (size_t)e * DD + h * CC;
        float s0 = 0.f, s1 = 0.f, s2 = 0.f, s3 = 0.f;
#pragma unroll
        for (int c = 0; c < CC; c += 4) {
            s0 += Ps[c + 0][d] * wr[c + 0];
            s1 += Ps[c + 1][d] * wr[c + 1];
            s2 += Ps[c + 2][d] * wr[c + 2];
            s3 += Ps[c + 3][d] * wr[c + 3];
        }
        g_w2[((size_t)b_ * DD + e) * DD + h * CC + d] =
            __uint_as_float(cvtu((s0 + s1) + (s2 + s3)));
    }
}

// ---------------------------------------------------------------------------
// K5: final[b,n,e] = sum_k v[b][k][n] * W2[b][e][k] + bias  via tf32 MMA
// (v and W2 pre-rounded -> no cvt in mainloop)
// grid (3 e-tiles, 25 n-tiles, 32 b); 128x128 tile
// ---------------------------------------------------------------------------
__global__ __launch_bounds__(256) void k_proj(const float* __restrict__ bias,
                                              float* __restrict__ out) {
    extern __shared__ float ds[];
    float (*As2)[32][136] = (float (*)[32][136])ds;
    float (*Bs)[128][36]  = (float (*)[128][36])(ds + 2 * 32 * 136);
    const int n0 = blockIdx.y * 128, e0 = blockIdx.x * 128;
    const int b_ = blockIdx.z;
    const int t = threadIdx.x, lane = t & 31, wid = t >> 5;
    const int wm = wid >> 2, wn = wid & 3;
    const int g = lane >> 2, tg = lane & 3;
    const int lr = t >> 3, ls = (t & 7) * 4;

    const float* vbase = g_qkv + (size_t)(2 * BH + b_ * HH) * CC * NN;
    const float* gw2 = g_w2 + ((size_t)b_ * DD + e0 + lr) * DD + ls;

    float acc[16][4];
#pragma unroll
    for (int i = 0; i < 16; i++)
#pragma unroll
        for (int j = 0; j < 4; j++) acc[i][j] = 0.f;

#define ISSUE_PROJ(buf, k0)                                                  \
    do {                                                                     \
        _Pragma("unroll")                                                    \
        for (int i = 0; i < 4; i++) {                                        \
            int idx = t + 256 * i;                                           \
            int kloc = idx >> 5, m4 = idx & 31;                              \
            int kg = (k0) + kloc;                                            \
            int nn = n0 + 4 * m4;                                            \
            if (nn > NN - 4) nn = NN - 4;                                    \
            cpa16(smem_u32(&As2[buf][kloc][4 * m4]),                         \
                  vbase + (size_t)kg * NN + nn);                             \
            cpa16(smem_u32(&Bs[buf][lr + 32 * i][ls]),                       \
                  gw2 + (size_t)(32 * i) * DD + (k0));                       \
        }                                                                    \
    } while (0)

    ISSUE_PROJ(0, 0);
    CPA_COMMIT();

    for (int ch = 0; ch < 12; ch++) {
        const int buf = ch & 1;
        if (ch < 11) {
            ISSUE_PROJ(buf ^ 1, (ch + 1) * 32);
            CPA_COMMIT();
            CPA_WAIT1();
        } else {
            CPA_WAIT0();
        }
        __syncthreads();
#pragma unroll
        for (int kk = 0; kk < 4; kk++) {
            unsigned a[4][4], b[4][2];
#pragma unroll
            for (int mi = 0; mi < 4; mi++) {
                int m = wm * 64 + mi * 16 + g;
                a[mi][0] = FU(As2[buf][kk * 8 + tg][m]);
                a[mi][1] = FU(As2[buf][kk * 8 + tg][m + 8]);
                a[mi][2] = FU(As2[buf][kk * 8 + tg + 4][m]);
                a[mi][3] = FU(As2[buf][kk * 8 + tg + 4][m + 8]);
            }
#pragma unroll
            for (int ni = 0; ni < 4; ni++) {
                int e = wn * 32 + ni * 8 + g;
                b[ni][0] = FU(Bs[buf][e][kk * 8 + tg]);
                b[ni][1] = FU(Bs[buf][e][kk * 8 + tg + 4]);
            }
#pragma unroll
            for (int mi = 0; mi < 4; mi++)
#pragma unroll
                for (int ni = 0; ni < 4; ni++)
                    mma_tf32(acc[mi * 4 + ni], a[mi], b[ni]);
        }
        __syncthreads();
    }
#undef ISSUE_PROJ

    // Epilogue: stage [mL][e] slabs, store e-contiguous + bias (mask n >= NN)
    float (*Cs)[132] = (float (*)[132])ds;   // 32 x 132
#pragma unroll 1
    for (int slab = 0; slab < 4; slab++) {
        if ((slab >> 1) == wm) {
#pragma unroll
            for (int mi2 = 0; mi2 < 2; mi2++) {
                int mi = (slab & 1) * 2 + mi2;
#pragma unroll
                for (int ni = 0; ni < 4; ni++) {
                    int mL = mi2 * 16 + g;
                    int e = wn * 32 + ni * 8 + 2 * tg;
                    float* a4 = acc[mi * 4 + ni];
                    Cs[mL][e]         = a4[0];
                    Cs[mL][e + 1]     = a4[1];
                    Cs[mL + 8][e]     = a4[2];
                    Cs[mL + 8][e + 1] = a4[3];
                }
            }
        }
        __syncthreads();
#pragma unroll
        for (int it = 0; it < 4; it++) {
            int idx = t + 256 * it;
            int mL = idx >> 5, f = idx & 31;
            int n = n0 + slab * 32 + mL;
            if (n < NN) {
                float4 v = *(float4*)&Cs[mL][4 * f];
                float4 bi = *(const float4*)(bias + e0 + 4 * f);
                v.x += bi.x; v.y += bi.y; v.z += bi.z; v.w += bi.w;
                *(float4*)(out + ((size_t)b_ * NN + n) * DD + e0 + 4 * f) = v;
            }
        }
        __syncthreads();
    }
}

// ---------------------------------------------------------------------------
#define SMEM_QKV (2 * 128 * 40 * 2 * 4)                  // 81920 B
#define SMEM_PROJ ((2 * 32 * 136 + 2 * 128 * 36) * 4)    // 71680 B

extern "C" void kernel_launch(void* const* d_in, const int* in_sizes, int n_in,
                              void* d_out, int out_size) {
    const float* x      = (const float*)d_in[0];
    const float* qkv_w  = (const float*)d_in[1];
    const float* temp   = (const float*)d_in[2];
    const float* proj_w = (const float*)d_in[3];
    const float* proj_b = (const float*)d_in[4];
    float* out = (float*)d_out;

    static int configured = 0;
    if (!configured) {
        cudaFuncSetAttribute(k_qkv,  cudaFuncAttributeMaxDynamicSharedMemorySize, SMEM_QKV);
        cudaFuncSetAttribute(k_proj, cudaFuncAttributeMaxDynamicSharedMemorySize, SMEM_PROJ);
        configured = 1;
    }

    k_cvt<<<4096, 256>>>(x, qkv_w);
    k_qkv<<<dim3(E3 / 128, ROWS / 128), 256, SMEM_QKV>>>();
    k_qk<<<dim3(BH, NSPLIT), 256>>>();
    k_softmax<<<BH, 64>>>(temp);
    k_wprime<<<dim3(BH, 3), 256>>>(proj_w);
    k_proj<<<dim3(DD / 128, (NN + 127) / 128, BB), 256, SMEM_PROJ>>>(proj_b, out);
}

// round 10
// speedup vs baseline: 1.1894x; 1.1894x over previous
#include <cuda_runtime.h>
#include <cuda_fp16.h>
#include <math.h>
#include <stdint.h>

#define BB 32
#define NN 3136
#define DD 384
#define HH 8
#define CC 48
#define BH 256          // BB*HH
#define ROWS 100352     // BB*NN
#define E3 1152         // 3*DD
#define NSPLIT 7
#define NCHUNK 448      // NN / NSPLIT

// Scratch (sanctioned __device__ globals; no allocations anywhere)
__device__ float g_qkv[(size_t)3 * BH * CC * NN];   // [3][bh][c][n]; v tf32-rounded
__device__ __half g_xh[(size_t)ROWS * DD];          // fp16-rounded x
__device__ __half g_wh[(size_t)E3 * DD];            // fp16-rounded qkv_w
__device__ float g_npart[(size_t)NSPLIT * BH * 96]; // sumsq partials (q rows, k rows)
__device__ float g_spart[(size_t)NSPLIT * BH * CC * CC];
__device__ float g_p[(size_t)BH * CC * CC];         // softmaxed attn
__device__ float g_w2[(size_t)BB * DD * DD];        // fused P@W weights, tf32-rounded

// ---------------------------------------------------------------------------
// helpers
// ---------------------------------------------------------------------------
__device__ __forceinline__ uint32_t smem_u32(const void* p) {
    uint32_t a;
    asm("{ .reg .u64 t; cvta.to.shared.u64 t, %1; cvt.u32.u64 %0, t; }"
        : "=r"(a) : "l"(p));
    return a;
}
__device__ __forceinline__ unsigned cvtu(float f) {   // fp32 -> tf32 bits (rna)
    unsigned r;
    asm("cvt.rna.tf32.f32 %0, %1;" : "=r"(r) : "f"(f));
    return r;
}
__device__ __forceinline__ void mma_tf32(float* c, const unsigned* a,
                                         const unsigned* b) {
    asm volatile(
        "mma.sync.aligned.m16n8k8.row.col.f32.tf32.tf32.f32 "
        "{%0,%1,%2,%3}, {%4,%5,%6,%7}, {%8,%9}, {%0,%1,%2,%3};\n"
        : "+f"(c[0]), "+f"(c[1]), "+f"(c[2]), "+f"(c[3])
        : "r"(a[0]), "r"(a[1]), "r"(a[2]), "r"(a[3]), "r"(b[0]), "r"(b[1]));
}
__device__ __forceinline__ void mma_f16(float* c, const unsigned* a,
                                        const unsigned* b) {
    asm volatile(
        "mma.sync.aligned.m16n8k16.row.col.f32.f16.f16.f32 "
        "{%0,%1,%2,%3}, {%4,%5,%6,%7}, {%8,%9}, {%0,%1,%2,%3};\n"
        : "+f"(c[0]), "+f"(c[1]), "+f"(c[2]), "+f"(c[3])
        : "r"(a[0]), "r"(a[1]), "r"(a[2]), "r"(a[3]), "r"(b[0]), "r"(b[1]));
}
__device__ __forceinline__ void cpa16(uint32_t s, const void* g) {
    asm volatile("cp.async.ca.shared.global [%0], [%1], 16;"
                 :: "r"(s), "l"(g) : "memory");
}
#define CPA_COMMIT() asm volatile("cp.async.commit_group;" ::: "memory")
#define CPA_WAIT1()  asm volatile("cp.async.wait_group 1;" ::: "memory")
#define CPA_WAIT0()  asm volatile("cp.async.wait_group 0;" ::: "memory")
#define FU(x) __float_as_uint(x)

// ---------------------------------------------------------------------------
// K0: round x and qkv_w to fp16 (rn) — feeds the fp16 qkv GEMM
// ---------------------------------------------------------------------------
__global__ __launch_bounds__(256) void k_cvt(const float* __restrict__ x,
                                             const float* __restrict__ w) {
    const size_t NX4 = (size_t)ROWS * DD / 4;
    const size_t NW4 = (size_t)E3 * DD / 4;
    for (size_t i = (size_t)blockIdx.x * 256 + threadIdx.x; i < NX4 + NW4;
         i += (size_t)gridDim.x * 256) {
        const float4 v = (i < NX4) ? ((const float4*)x)[i]
                                   : ((const float4*)w)[i - NX4];
        __half2 h0 = __floats2half2_rn(v.x, v.y);
        __half2 h1 = __floats2half2_rn(v.z, v.w);
        uint2 pk = make_uint2(*(uint32_t*)&h0, *(uint32_t*)&h1);
        if (i < NX4) ((uint2*)g_xh)[i] = pk;
        else         ((uint2*)g_wh)[i - NX4] = pk;
    }
}

// ---------------------------------------------------------------------------
// K1: qkv = xh @ wh^T via fp16 m16n8k16 MMA + cp.async double buffering.
// 128x128 tile, 12 K-chunks of 32; fp16 tiles, rows padded to 40 halfs.
// ---------------------------------------------------------------------------
__global__ __launch_bounds__(256) void k_qkv() {
    extern __shared__ __align__(16) unsigned char dsraw[];
    __half (*As)[128][40] = (__half (*)[128][40])dsraw;
    __half (*Bs)[128][40] = (__half (*)[128][40])(dsraw + 2 * 128 * 40 * 2);
    float* ds = (float*)dsraw;
    const int m0 = blockIdx.y * 128, e0 = blockIdx.x * 128;
    const int t = threadIdx.x, lane = t & 31, wid = t >> 5;
    const int wm = wid >> 2, wn = wid & 3;
    const int g = lane >> 2, tg = lane & 3;

    // loader mapping: idx = t + 256*i (i<2): row = idx>>2, seg = idx&3 (16B segs)
    const int lrow0 = t >> 2, lseg0 = t & 3;
    const int lrow1 = (t + 256) >> 2, lseg1 = (t + 256) & 3;
    const __half* gx0 = g_xh + (size_t)(m0 + lrow0) * DD + lseg0 * 8;
    const __half* gx1 = g_xh + (size_t)(m0 + lrow1) * DD + lseg1 * 8;
    const __half* gw0 = g_wh + (size_t)(e0 + lrow0) * DD + lseg0 * 8;
    const __half* gw1 = g_wh + (size_t)(e0 + lrow1) * DD + lseg1 * 8;

    float acc[16][4];
#pragma unroll
    for (int i = 0; i < 16; i++)
#pragma unroll
        for (int j = 0; j < 4; j++) acc[i][j] = 0.f;

#define ISSUE_QKV(buf, k0)                                                   \
    do {                                                                     \
        cpa16(smem_u32(&As[buf][lrow0][lseg0 * 8]), gx0 + (k0));             \
        cpa16(smem_u32(&As[buf][lrow1][lseg1 * 8]), gx1 + (k0));             \
        cpa16(smem_u32(&Bs[buf][lrow0][lseg0 * 8]), gw0 + (k0));             \
        cpa16(smem_u32(&Bs[buf][lrow1][lseg1 * 8]), gw1 + (k0));             \
    } while (0)

    ISSUE_QKV(0, 0);
    CPA_COMMIT();

    for (int ch = 0; ch < 12; ch++) {
        const int buf = ch & 1;
        if (ch < 11) {
            ISSUE_QKV(buf ^ 1, (ch + 1) * 32);
            CPA_COMMIT();
            CPA_WAIT1();
        } else {
            CPA_WAIT0();
        }
        __syncthreads();
#pragma unroll
        for (int kk = 0; kk < 2; kk++) {
            const int kb = kk * 16 + 2 * tg;
            unsigned a[4][4], b[4][2];
#pragma unroll
            for (int mi = 0; mi < 4; mi++) {
                int m = wm * 64 + mi * 16 + g;
                a[mi][0] = *(const uint32_t*)&As[buf][m][kb];
                a[mi][1] = *(const uint32_t*)&As[buf][m + 8][kb];
                a[mi][2] = *(const uint32_t*)&As[buf][m][kb + 8];
                a[mi][3] = *(const uint32_t*)&As[buf][m + 8][kb + 8];
            }
#pragma unroll
            for (int ni = 0; ni < 4; ni++) {
                int e = wn * 32 + ni * 8 + g;
                b[ni][0] = *(const uint32_t*)&Bs[buf][e][kb];
                b[ni][1] = *(const uint32_t*)&Bs[buf][e][kb + 8];
            }
#pragma unroll
            for (int mi = 0; mi < 4; mi++)
#pragma unroll
                for (int ni = 0; ni < 4; ni++)
                    mma_f16(acc[mi * 4 + ni], a[mi], b[ni]);
        }
        __syncthreads();
    }
#undef ISSUE_QKV

    // Epilogue: stage [eL][m] slabs in smem, stream n-contiguous scatter;
    // v (s==2) rounded to tf32 so k_proj can skip cvt.
    float (*Cs)[132] = (float (*)[132])ds;   // 32 x 132
#pragma unroll 1
    for (int slab = 0; slab < 4; slab++) {
        if (wn == slab) {
#pragma unroll
            for (int mi = 0; mi < 4; mi++)
#pragma unroll
                for (int ni = 0; ni < 4; ni++) {
                    int eL = ni * 8 + 2 * tg;
                    int m = wm * 64 + mi * 16 + g;
                    float* a4 = acc[mi * 4 + ni];
                    Cs[eL][m]         = a4[0];
                    Cs[eL + 1][m]     = a4[1];
                    Cs[eL][m + 8]     = a4[2];
                    Cs[eL + 1][m + 8] = a4[3];
                }
        }
        __syncthreads();
#pragma unroll
        for (int it = 0; it < 4; it++) {
            int idx = t + 256 * it;          // 0..1023
            int eL = idx >> 5, f = idx & 31;
            int e = e0 + slab * 32 + eL;
            int s = e / DD;
            int rem = e - s * DD;
            int h = rem / CC;
            int c = rem - h * CC;
            int m = m0 + 4 * f;
            int b_ = m / NN;
            int n = m - b_ * NN;
            float4 vv = *(float4*)&Cs[eL][4 * f];
            if (s == 2) {
                vv.x = __uint_as_float(cvtu(vv.x));
                vv.y = __uint_as_float(cvtu(vv.y));
                vv.z = __uint_as_float(cvtu(vv.z));
                vv.w = __uint_as_float(cvtu(vv.w));
            }
            *(float4*)(g_qkv + ((size_t)((s * BB + b_) * HH + h) * CC + c) * NN + n) = vv;
        }
        __syncthreads();
    }
}

// ---------------------------------------------------------------------------
// K3a: partial S[c][d] = sum_n q[c][n] k[d][n] over an n-chunk
//      + fused per-row sumsq partials (threads 0..95)
// ---------------------------------------------------------------------------
__global__ __launch_bounds__(256) void k_qk() {
    __shared__ float qs[48][68];
    __shared__ float ks[48][68];
    const int bh = blockIdx.x;
    const int n0 = blockIdx.y * NCHUNK;
    const int t  = threadIdx.x;
    const int ci = t >> 4, dj = t & 15;

    const float* qb = g_qkv + (size_t)bh * CC * NN;
    const float* kb = g_qkv + (size_t)(BH + bh) * CC * NN;

    float acc[3][3] = {};
    float nacc = 0.f;
    for (int cc = 0; cc < NCHUNK; cc += 64) {
        int nb = n0 + cc;
#pragma unroll
        for (int jj = 0; jj < 3; jj++) {
            int idx = t + 256 * jj;
            int c = idx >> 4, f = idx & 15;
            *(float4*)&qs[c][4 * f] = *(const float4*)(qb + (size_t)c * NN + nb + 4 * f);
            *(float4*)&ks[c][4 * f] = *(const float4*)(kb + (size_t)c * NN + nb + 4 * f);
        }
        __syncthreads();
        if (t < 96) {
            const float4* rowp = (t < 48) ? (const float4*)&qs[t][0]
                                          : (const float4*)&ks[t - 48][0];
#pragma unroll
            for (int f = 0; f < 16; f++) {
                float4 v = rowp[f];
                nacc += v.x * v.x + v.y * v.y + v.z * v.z + v.w * v.w;
            }
        }
#pragma unroll 8
        for (int nn = 0; nn < 64; nn++) {
            float a0 = qs[3 * ci + 0][nn];
            float a1 = qs[3 * ci + 1][nn];
            float a2 = qs[3 * ci + 2][nn];
            float b0 = ks[3 * dj + 0][nn];
            float b1 = ks[3 * dj + 1][nn];
            float b2 = ks[3 * dj + 2][nn];
            acc[0][0] += a0 * b0; acc[0][1] += a0 * b1; acc[0][2] += a0 * b2;
            acc[1][0] += a1 * b0; acc[1][1] += a1 * b1; acc[1][2] += a1 * b2;
            acc[2][0] += a2 * b0; acc[2][1] += a2 * b1; acc[2][2] += a2 * b2;
        }
        __syncthreads();
    }
    float* out = g_spart + ((size_t)blockIdx.y * BH + bh) * (CC * CC);
#pragma unroll
    for (int i = 0; i < 3; i++)
#pragma unroll
        for (int j = 0; j < 3; j++)
            out[(3 * ci + i) * CC + (3 * dj + j)] = acc[i][j];
    if (t < 96)
        g_npart[((size_t)blockIdx.y * BH + bh) * 96 + t] = nacc;
}

// ---------------------------------------------------------------------------
// K3b: reduce partials (S and norms), scale, row softmax -> g_p
// ---------------------------------------------------------------------------
__global__ __launch_bounds__(64) void k_softmax(const float* __restrict__ temp) {
    __shared__ float S[48][48];
    __shared__ float inorm[96];
    const int bh = blockIdx.x;
    const int t  = threadIdx.x;
    const float tp = temp[bh % HH];
    for (int r = t; r < 96; r += 64) {
        float s = 0.f;
#pragma unroll
        for (int p = 0; p < NSPLIT; p++)
            s += g_npart[((size_t)p * BH + bh) * 96 + r];
        inorm[r] = 1.f / fmaxf(sqrtf(s), 1e-12f);
    }
    __syncthreads();
    for (int idx = t; idx < CC * CC; idx += 64) {
        float s = 0.f;
#pragma unroll
        for (int p = 0; p < NSPLIT; p++)
            s += g_spart[((size_t)p * BH + bh) * (CC * CC) + idx];
        int c = idx / CC, d = idx - c * CC;
        s *= inorm[c] * inorm[48 + d] * tp;
        S[c][d] = s;
    }
    __syncthreads();
    if (t < 48) {
        float mx = -1e30f;
#pragma unroll
        for (int d = 0; d < 48; d++) mx = fmaxf(mx, S[t][d]);
        float sum = 0.f;
#pragma unroll
        for (int d = 0; d < 48; d++) {
            float e = __expf(S[t][d] - mx);
            S[t][d] = e;
            sum += e;
        }
        float inv = 1.f / sum;
#pragma unroll
        for (int d = 0; d < 48; d++)
            g_p[(size_t)bh * (CC * CC) + t * CC + d] = S[t][d] * inv;
    }
}

// ---------------------------------------------------------------------------
// K_W2: W2[b][e][h*48+d] = sum_c P[b,h,c,d] * W[e][h*48+c]  (tf32-rounded out)
// grid (BH, 3); 4 independent c-partials per output for ILP
// ---------------------------------------------------------------------------
__global__ __launch_bounds__(256) void k_wprime(const float* __restrict__ w) {
    __shared__ float Ps[48][49];   // [c][d]
    const int bh = blockIdx.x;
    const int b_ = bh / HH, h = bh % HH;
    const int eseg = blockIdx.y;   // 0..2, 128 e each
    const int t = threadIdx.x;
    for (int idx = t; idx < CC * CC; idx += 256) {
        int c = idx / CC;
        Ps[c][idx - c * CC] = g_p[(size_t)bh * (CC * CC) + idx];
    }
    __syncthreads();
    for (int idx = t; idx < 128 * CC; idx += 256) {
        int eL = idx / CC, d = idx - (idx / CC) * CC;
        int e = eseg * 128 + eL;
        const float* wr = w + (size_t)e * DD + h * CC;
        float s0 = 0.f, s1 = 0.f, s2 = 0.f, s3 = 0.f;
#pragma unroll
        for (int c = 0; c < CC; c += 4) {
            s0 += Ps[c + 0][d] * wr[c + 0];
            s1 += Ps[c + 1][d] * wr[c + 1];
            s2 += Ps[c + 2][d] * wr[c + 2];
            s3 += Ps[c + 3][d] * wr[c + 3];
        }
        g_w2[((size_t)b_ * DD + e) * DD + h * CC + d] =
            __uint_as_float(cvtu((s0 + s1) + (s2 + s3)));
    }
}

// ---------------------------------------------------------------------------
// K5: final[b,n,e] = sum_k v[b][k][n] * W2[b][e][k] + bias  via tf32 MMA
// (v and W2 pre-rounded -> no cvt in mainloop)
// grid (3 e-tiles, 25 n-tiles, 32 b); 128x128 tile
// ---------------------------------------------------------------------------
__global__ __launch_bounds__(256) void k_proj(const float* __restrict__ bias,
                                              float* __restrict__ out) {
    extern __shared__ float ds[];
    float (*As2)[32][136] = (float (*)[32][136])ds;
    float (*Bs)[128][36]  = (float (*)[128][36])(ds + 2 * 32 * 136);
    const int n0 = blockIdx.y * 128, e0 = blockIdx.x * 128;
    const int b_ = blockIdx.z;
    const int t = threadIdx.x, lane = t & 31, wid = t >> 5;
    const int wm = wid >> 2, wn = wid & 3;
    const int g = lane >> 2, tg = lane & 3;
    const int lr = t >> 3, ls = (t & 7) * 4;

    const float* vbase = g_qkv + (size_t)(2 * BH + b_ * HH) * CC * NN;
    const float* gw2 = g_w2 + ((size_t)b_ * DD + e0 + lr) * DD + ls;

    float acc[16][4];
#pragma unroll
    for (int i = 0; i < 16; i++)
#pragma unroll
        for (int j = 0; j < 4; j++) acc[i][j] = 0.f;

#define ISSUE_PROJ(buf, k0)                                                  \
    do {                                                                     \
        _Pragma("unroll")                                                    \
        for (int i = 0; i < 4; i++) {                                        \
            int idx = t + 256 * i;                                           \
            int kloc = idx >> 5, m4 = idx & 31;                              \
            int kg = (k0) + kloc;                                            \
            int nn = n0 + 4 * m4;                                            \
            if (nn > NN - 4) nn = NN - 4;                                    \
            cpa16(smem_u32(&As2[buf][kloc][4 * m4]),                         \
                  vbase + (size_t)kg * NN + nn);                             \
            cpa16(smem_u32(&Bs[buf][lr + 32 * i][ls]),                       \
                  gw2 + (size_t)(32 * i) * DD + (k0));                       \
        }                                                                    \
    } while (0)

    ISSUE_PROJ(0, 0);
    CPA_COMMIT();

    for (int ch = 0; ch < 12; ch++) {
        const int buf = ch & 1;
        if (ch < 11) {
            ISSUE_PROJ(buf ^ 1, (ch + 1) * 32);
            CPA_COMMIT();
            CPA_WAIT1();
        } else {
            CPA_WAIT0();
        }
        __syncthreads();
#pragma unroll
        for (int kk = 0; kk < 4; kk++) {
            unsigned a[4][4], b[4][2];
#pragma unroll
            for (int mi = 0; mi < 4; mi++) {
                int m = wm * 64 + mi * 16 + g;
                a[mi][0] = FU(As2[buf][kk * 8 + tg][m]);
                a[mi][1] = FU(As2[buf][kk * 8 + tg][m + 8]);
                a[mi][2] = FU(As2[buf][kk * 8 + tg + 4][m]);
                a[mi][3] = FU(As2[buf][kk * 8 + tg + 4][m + 8]);
            }
#pragma unroll
            for (int ni = 0; ni < 4; ni++) {
                int e = wn * 32 + ni * 8 + g;
                b[ni][0] = FU(Bs[buf][e][kk * 8 + tg]);
                b[ni][1] = FU(Bs[buf][e][kk * 8 + tg + 4]);
            }
#pragma unroll
            for (int mi = 0; mi < 4; mi++)
#pragma unroll
                for (int ni = 0; ni < 4; ni++)
                    mma_tf32(acc[mi * 4 + ni], a[mi], b[ni]);
        }
        __syncthreads();
    }
#undef ISSUE_PROJ

    // Epilogue: stage [mL][e] slabs, store e-contiguous + bias (mask n >= NN)
    float (*Cs)[132] = (float (*)[132])ds;   // 32 x 132
#pragma unroll 1
    for (int slab = 0; slab < 4; slab++) {
        if ((slab >> 1) == wm) {
#pragma unroll
            for (int mi2 = 0; mi2 < 2; mi2++) {
                int mi = (slab & 1) * 2 + mi2;
#pragma unroll
                for (int ni = 0; ni < 4; ni++) {
                    int mL = mi2 * 16 + g;
                    int e = wn * 32 + ni * 8 + 2 * tg;
                    float* a4 = acc[mi * 4 + ni];
                    Cs[mL][e]         = a4[0];
                    Cs[mL][e + 1]     = a4[1];
                    Cs[mL + 8][e]     = a4[2];
                    Cs[mL + 8][e + 1] = a4[3];
                }
            }
        }
        __syncthreads();
#pragma unroll
        for (int it = 0; it < 4; it++) {
            int idx = t + 256 * it;
            int mL = idx >> 5, f = idx & 31;
            int n = n0 + slab * 32 + mL;
            if (n < NN) {
                float4 v = *(float4*)&Cs[mL][4 * f];
                float4 bi = *(const float4*)(bias + e0 + 4 * f);
                v.x += bi.x; v.y += bi.y; v.z += bi.z; v.w += bi.w;
                *(float4*)(out + ((size_t)b_ * NN + n) * DD + e0 + 4 * f) = v;
            }
        }
        __syncthreads();
    }
}

// ---------------------------------------------------------------------------
#define SMEM_QKV (2 * 128 * 40 * 2 * 2)                  // 40960 B (fp16 tiles)
#define SMEM_PROJ ((2 * 32 * 136 + 2 * 128 * 36) * 4)    // 71680 B

extern "C" void kernel_launch(void* const* d_in, const int* in_sizes, int n_in,
                              void* d_out, int out_size) {
    const float* x      = (const float*)d_in[0];
    const float* qkv_w  = (const float*)d_in[1];
    const float* temp   = (const float*)d_in[2];
    const float* proj_w = (const float*)d_in[3];
    const float* proj_b = (const float*)d_in[4];
    float* out = (float*)d_out;

    static int configured = 0;
    if (!configured) {
        cudaFuncSetAttribute(k_qkv,  cudaFuncAttributeMaxDynamicSharedMemorySize, SMEM_QKV);
        cudaFuncSetAttribute(k_proj, cudaFuncAttributeMaxDynamicSharedMemorySize, SMEM_PROJ);
        configured = 1;
    }

    k_cvt<<<4096, 256>>>(x, qkv_w);
    k_qkv<<<dim3(E3 / 128, ROWS / 128), 256, SMEM_QKV>>>();
    k_qk<<<dim3(BH, NSPLIT), 256>>>();
    k_softmax<<<BH, 64>>>(temp);
    k_wprime<<<dim3(BH, 3), 256>>>(proj_w);
    k_proj<<<dim3(DD / 128, (NN + 127) / 128, BB), 256, SMEM_PROJ>>>(proj_b, out);
}

// round 13
// speedup vs baseline: 1.5174x; 1.2758x over previous
#include <cuda_runtime.h>
#include <cuda_fp16.h>
#include <math.h>
#include <stdint.h>

#define BB 32
#define NN 3136
#define DD 384
#define HH 8
#define CC 48
#define BH 256          // BB*HH
#define ROWS 100352     // BB*NN
#define E3 1152         // 3*DD
#define NSPLIT 7
#define NCHUNK 448      // NN / NSPLIT

// Scratch (sanctioned __device__ globals; no allocations anywhere)
__device__ float g_qkv[(size_t)2 * BH * CC * NN];   // q,k fp32 [2][bh][c][n]
__device__ __half g_vh[(size_t)BH * CC * NN];       // v fp16 [bh][c][n]
__device__ __half g_xh[(size_t)ROWS * DD];          // fp16-rounded x
__device__ __half g_wh[(size_t)E3 * DD];            // fp16-rounded qkv_w
__device__ float g_npart[(size_t)NSPLIT * BH * 96]; // sumsq partials (q rows, k rows)
__device__ float g_spart[(size_t)NSPLIT * BH * CC * CC];
__device__ float g_p[(size_t)BH * CC * CC];         // softmaxed attn
__device__ __half g_w2h[(size_t)BB * DD * DD];      // fused P@W weights fp16 [b][e][k]

// ---------------------------------------------------------------------------
// helpers
// ---------------------------------------------------------------------------
__device__ __forceinline__ uint32_t smem_u32(const void* p) {
    uint32_t a;
    asm("{ .reg .u64 t; cvta.to.shared.u64 t, %1; cvt.u32.u64 %0, t; }"
        : "=r"(a) : "l"(p));
    return a;
}
__device__ __forceinline__ void mma_f16(float* c, const unsigned* a,
                                        const unsigned* b) {
    asm volatile(
        "mma.sync.aligned.m16n8k16.row.col.f32.f16.f16.f32 "
        "{%0,%1,%2,%3}, {%4,%5,%6,%7}, {%8,%9}, {%0,%1,%2,%3};\n"
        : "+f"(c[0]), "+f"(c[1]), "+f"(c[2]), "+f"(c[3])
        : "r"(a[0]), "r"(a[1]), "r"(a[2]), "r"(a[3]), "r"(b[0]), "r"(b[1]));
}
__device__ __forceinline__ void ldsm4t(unsigned* r, uint32_t addr) {
    asm volatile(
        "ldmatrix.sync.aligned.m8n8.x4.trans.shared.b16 {%0,%1,%2,%3}, [%4];"
        : "=r"(r[0]), "=r"(r[1]), "=r"(r[2]), "=r"(r[3]) : "r"(addr));
}
__device__ __forceinline__ void cpa16(uint32_t s, const void* g) {
    asm volatile("cp.async.ca.shared.global [%0], [%1], 16;"
                 :: "r"(s), "l"(g) : "memory");
}
#define CPA_COMMIT() asm volatile("cp.async.commit_group;" ::: "memory")
#define CPA_WAIT1()  asm volatile("cp.async.wait_group 1;" ::: "memory")
#define CPA_WAIT0()  asm volatile("cp.async.wait_group 0;" ::: "memory")

// ---------------------------------------------------------------------------
// K0: round x and qkv_w to fp16 (rn) — feeds the fp16 qkv GEMM
// ---------------------------------------------------------------------------
__global__ __launch_bounds__(256) void k_cvt(const float* __restrict__ x,
                                             const float* __restrict__ w) {
    const size_t NX4 = (size_t)ROWS * DD / 4;
    const size_t NW4 = (size_t)E3 * DD / 4;
    for (size_t i = (size_t)blockIdx.x * 256 + threadIdx.x; i < NX4 + NW4;
         i += (size_t)gridDim.x * 256) {
        const float4 v = (i < NX4) ? ((const float4*)x)[i]
                                   : ((const float4*)w)[i - NX4];
        __half2 h0 = __floats2half2_rn(v.x, v.y);
        __half2 h1 = __floats2half2_rn(v.z, v.w);
        uint2 pk = make_uint2(*(uint32_t*)&h0, *(uint32_t*)&h1);
        if (i < NX4) ((uint2*)g_xh)[i] = pk;
        else         ((uint2*)g_wh)[i - NX4] = pk;
    }
}

// ---------------------------------------------------------------------------
// K1: qkv = xh @ wh^T via fp16 m16n8k16 MMA + cp.async double buffering.
// 128x128 tile, 12 K-chunks of 32; fp16 tiles, rows padded to 40 halfs.
// q,k stored fp32 to g_qkv; v stored fp16 to g_vh.
// ---------------------------------------------------------------------------
__global__ __launch_bounds__(256) void k_qkv() {
    extern __shared__ __align__(16) unsigned char dsraw[];
    __half (*As)[128][40] = (__half (*)[128][40])dsraw;
    __half (*Bs)[128][40] = (__half (*)[128][40])(dsraw + 2 * 128 * 40 * 2);
    float* ds = (float*)dsraw;
    const int m0 = blockIdx.y * 128, e0 = blockIdx.x * 128;
    const int t = threadIdx.x, lane = t & 31, wid = t >> 5;
    const int wm = wid >> 2, wn = wid & 3;
    const int g = lane >> 2, tg = lane & 3;

    const int lrow0 = t >> 2, lseg0 = t & 3;
    const int lrow1 = (t + 256) >> 2, lseg1 = (t + 256) & 3;
    const __half* gx0 = g_xh + (size_t)(m0 + lrow0) * DD + lseg0 * 8;
    const __half* gx1 = g_xh + (size_t)(m0 + lrow1) * DD + lseg1 * 8;
    const __half* gw0 = g_wh + (size_t)(e0 + lrow0) * DD + lseg0 * 8;
    const __half* gw1 = g_wh + (size_t)(e0 + lrow1) * DD + lseg1 * 8;

    float acc[16][4];
#pragma unroll
    for (int i = 0; i < 16; i++)
#pragma unroll
        for (int j = 0; j < 4; j++) acc[i][j] = 0.f;

#define ISSUE_QKV(buf, k0)                                                   \
    do {                                                                     \
        cpa16(smem_u32(&As[buf][lrow0][lseg0 * 8]), gx0 + (k0));             \
        cpa16(smem_u32(&As[buf][lrow1][lseg1 * 8]), gx1 + (k0));             \
        cpa16(smem_u32(&Bs[buf][lrow0][lseg0 * 8]), gw0 + (k0));             \
        cpa16(smem_u32(&Bs[buf][lrow1][lseg1 * 8]), gw1 + (k0));             \
    } while (0)

    ISSUE_QKV(0, 0);
    CPA_COMMIT();

    for (int ch = 0; ch < 12; ch++) {
        const int buf = ch & 1;
        if (ch < 11) {
            ISSUE_QKV(buf ^ 1, (ch + 1) * 32);
            CPA_COMMIT();
            CPA_WAIT1();
        } else {
            CPA_WAIT0();
        }
        __syncthreads();
#pragma unroll
        for (int kk = 0; kk < 2; kk++) {
            const int kb = kk * 16 + 2 * tg;
            unsigned a[4][4], b[4][2];
#pragma unroll
            for (int mi = 0; mi < 4; mi++) {
                int m = wm * 64 + mi * 16 + g;
                a[mi][0] = *(const uint32_t*)&As[buf][m][kb];
                a[mi][1] = *(const uint32_t*)&As[buf][m + 8][kb];
                a[mi][2] = *(const uint32_t*)&As[buf][m][kb + 8];
                a[mi][3] = *(const uint32_t*)&As[buf][m + 8][kb + 8];
            }
#pragma unroll
            for (int ni = 0; ni < 4; ni++) {
                int e = wn * 32 + ni * 8 + g;
                b[ni][0] = *(const uint32_t*)&Bs[buf][e][kb];
                b[ni][1] = *(const uint32_t*)&Bs[buf][e][kb + 8];
            }
#pragma unroll
            for (int mi = 0; mi < 4; mi++)
#pragma unroll
                for (int ni = 0; ni < 4; ni++)
                    mma_f16(acc[mi * 4 + ni], a[mi], b[ni]);
        }
        __syncthreads();
    }
#undef ISSUE_QKV

    // Epilogue: stage [eL][m] slabs in smem; q,k -> fp32 scatter, v -> fp16
    float (*Cs)[132] = (float (*)[132])ds;   // 32 x 132
#pragma unroll 1
    for (int slab = 0; slab < 4; slab++) {
        if (wn == slab) {
#pragma unroll
            for (int mi = 0; mi < 4; mi++)
#pragma unroll
                for (int ni = 0; ni < 4; ni++) {
                    int eL = ni * 8 + 2 * tg;
                    int m = wm * 64 + mi * 16 + g;
                    float* a4 = acc[mi * 4 + ni];
                    Cs[eL][m]         = a4[0];
                    Cs[eL + 1][m]     = a4[1];
                    Cs[eL][m + 8]     = a4[2];
                    Cs[eL + 1][m + 8] = a4[3];
                }
        }
        __syncthreads();
#pragma unroll
        for (int it = 0; it < 4; it++) {
            int idx = t + 256 * it;          // 0..1023
            int eL = idx >> 5, f = idx & 31;
            int e = e0 + slab * 32 + eL;
            int s = e / DD;
            int rem = e - s * DD;
            int h = rem / CC;
            int c = rem - h * CC;
            int m = m0 + 4 * f;
            int b_ = m / NN;
            int n = m - b_ * NN;
            float4 vv = *(float4*)&Cs[eL][4 * f];
            if (s == 2) {
                __half2 h0 = __floats2half2_rn(vv.x, vv.y);
                __half2 h1 = __floats2half2_rn(vv.z, vv.w);
                uint2 pk = make_uint2(*(uint32_t*)&h0, *(uint32_t*)&h1);
                *(uint2*)(g_vh + ((size_t)(b_ * HH + h) * CC + c) * NN + n) = pk;
            } else {
                *(float4*)(g_qkv +
                    ((size_t)((s * BB + b_) * HH + h) * CC + c) * NN + n) = vv;
            }
        }
        __syncthreads();
    }
}

// ---------------------------------------------------------------------------
// K3a: partial S[c][d] = sum_n q[c][n] k[d][n] over an n-chunk
//      + fused per-row sumsq partials (threads 0..95)
// ---------------------------------------------------------------------------
__global__ __launch_bounds__(256) void k_qk() {
    __shared__ float qs[48][68];
    __shared__ float ks[48][68];
    const int bh = blockIdx.x;
    const int n0 = blockIdx.y * NCHUNK;
    const int t  = threadIdx.x;
    const int ci = t >> 4, dj = t & 15;

    const float* qb = g_qkv + (size_t)bh * CC * NN;
    const float* kb = g_qkv + (size_t)(BH + bh) * CC * NN;

    float acc[3][3] = {};
    float nacc = 0.f;
    for (int cc = 0; cc < NCHUNK; cc += 64) {
        int nb = n0 + cc;
#pragma unroll
        for (int jj = 0; jj < 3; jj++) {
            int idx = t + 256 * jj;
            int c = idx >> 4, f = idx & 15;
            *(float4*)&qs[c][4 * f] = *(const float4*)(qb + (size_t)c * NN + nb + 4 * f);
            *(float4*)&ks[c][4 * f] = *(const float4*)(kb + (size_t)c * NN + nb + 4 * f);
        }
        __syncthreads();
        if (t < 96) {
            const float4* rowp = (t < 48) ? (const float4*)&qs[t][0]
                                          : (const float4*)&ks[t - 48][0];
#pragma unroll
            for (int f = 0; f < 16; f++) {
                float4 v = rowp[f];
                nacc += v.x * v.x + v.y * v.y + v.z * v.z + v.w * v.w;
            }
        }
#pragma unroll 8
        for (int nn = 0; nn < 64; nn++) {
            float a0 = qs[3 * ci + 0][nn];
            float a1 = qs[3 * ci + 1][nn];
            float a2 = qs[3 * ci + 2][nn];
            float b0 = ks[3 * dj + 0][nn];
            float b1 = ks[3 * dj + 1][nn];
            float b2 = ks[3 * dj + 2][nn];
            acc[0][0] += a0 * b0; acc[0][1] += a0 * b1; acc[0][2] += a0 * b2;
            acc[1][0] += a1 * b0; acc[1][1] += a1 * b1; acc[1][2] += a1 * b2;
            acc[2][0] += a2 * b0; acc[2][1] += a2 * b1; acc[2][2] += a2 * b2;
        }
        __syncthreads();
    }
    float* out = g_spart + ((size_t)blockIdx.y * BH + bh) * (CC * CC);
#pragma unroll
    for (int i = 0; i < 3; i++)
#pragma unroll
        for (int j = 0; j < 3; j++)
            out[(3 * ci + i) * CC + (3 * dj + j)] = acc[i][j];
    if (t < 96)
        g_npart[((size_t)blockIdx.y * BH + bh) * 96 + t] = nacc;
}

// ---------------------------------------------------------------------------
// K3b: reduce partials (S and norms), scale, row softmax -> g_p
// ---------------------------------------------------------------------------
__global__ __launch_bounds__(64) void k_softmax(const float* __restrict__ temp) {
    __shared__ float S[48][48];
    __shared__ float inorm[96];
    const int bh = blockIdx.x;
    const int t  = threadIdx.x;
    const float tp = temp[bh % HH];
    for (int r = t; r < 96; r += 64) {
        float s = 0.f;
#pragma unroll
        for (int p = 0; p < NSPLIT; p++)
            s += g_npart[((size_t)p * BH + bh) * 96 + r];
        inorm[r] = 1.f / fmaxf(sqrtf(s), 1e-12f);
    }
    __syncthreads();
    for (int idx = t; idx < CC * CC; idx += 64) {
        float s = 0.f;
#pragma unroll
        for (int p = 0; p < NSPLIT; p++)
            s += g_spart[((size_t)p * BH + bh) * (CC * CC) + idx];
        int c = idx / CC, d = idx - c * CC;
        s *= inorm[c] * inorm[48 + d] * tp;
        S[c][d] = s;
    }
    __syncthreads();
    if (t < 48) {
        float mx = -1e30f;
#pragma unroll
        for (int d = 0; d < 48; d++) mx = fmaxf(mx, S[t][d]);
        float sum = 0.f;
#pragma unroll
        for (int d = 0; d < 48; d++) {
            float e = __expf(S[t][d] - mx);
            S[t][d] = e;
            sum += e;
        }
        float inv = 1.f / sum;
#pragma unroll
        for (int d = 0; d < 48; d++)
            g_p[(size_t)bh * (CC * CC) + t * CC + d] = S[t][d] * inv;
    }
}

// ---------------------------------------------------------------------------
// K_W2: W2[b][e][h*48+d] = sum_c P[b,h,c,d] * W[e][h*48+c]  -> fp16
// grid (BH, 3); 4 independent c-partials per output for ILP
// ---------------------------------------------------------------------------
__global__ __launch_bounds__(256) void k_wprime(const float* __restrict__ w) {
    __shared__ float Ps[48][49];   // [c][d]
    const int bh = blockIdx.x;
    const int b_ = bh / HH, h = bh % HH;
    const int eseg = blockIdx.y;   // 0..2, 128 e each
    const int t = threadIdx.x;
    for (int idx = t; idx < CC * CC; idx += 256) {
        int c = idx / CC;
        Ps[c][idx - c * CC] = g_p[(size_t)bh * (CC * CC) + idx];
    }
    __syncthreads();
    for (int idx = t; idx < 128 * CC; idx += 256) {
        int eL = idx / CC, d = idx - (idx / CC) * CC;
        int e = eseg * 128 + eL;
        const float* wr = w + (size_t)e * DD + h * CC;
        float s0 = 0.f, s1 = 0.f, s2 = 0.f, s3 = 0.f;
#pragma unroll
        for (int c = 0; c < CC; c += 4) {
            s0 += Ps[c + 0][d] * wr[c + 0];
            s1 += Ps[c + 1][d] * wr[c + 1];
            s2 += Ps[c + 2][d] * wr[c + 2];
            s3 += Ps[c + 3][d] * wr[c + 3];
        }
        g_w2h[((size_t)b_ * DD + e) * DD + h * CC + d] =
            __float2half_rn((s0 + s1) + (s2 + s3));
    }
}

// ---------------------------------------------------------------------------
// K5: final[b,n,e] = sum_k v[b][k][n] * W2[b][e][k] + bias  via fp16 MMA
// A (V) staged [k][n] fp16, loaded with ldmatrix.x4.trans; B (W2) [e][k] fp16.
// grid (3 e-tiles, 25 n-tiles, 32 b); 128x128 tile, K chunks of 32
// ---------------------------------------------------------------------------
__global__ __launch_bounds__(256) void k_proj(const float* __restrict__ bias,
                                              float* __restrict__ out) {
    extern __shared__ __align__(16) unsigned char dsraw[];
    __half (*Ah)[32][136] = (__half (*)[32][136])dsraw;            // [k][n]
    __half (*Bh)[128][40] = (__half (*)[128][40])(dsraw + 2 * 32 * 136 * 2);
    float* ds = (float*)dsraw;
    const int n0 = blockIdx.y * 128, e0 = blockIdx.x * 128;
    const int b_ = blockIdx.z;
    const int t = threadIdx.x, lane = t & 31, wid = t >> 5;
    const int wm = wid >> 2, wn = wid & 3;
    const int g = lane >> 2, tg = lane & 3;

    const __half* vbase = g_vh + (size_t)(b_ * HH) * CC * NN;
    const __half* w2base = g_w2h + (size_t)b_ * DD * DD;

    float acc[16][4];
#pragma unroll
    for (int i = 0; i < 16; i++)
#pragma unroll
        for (int j = 0; j < 4; j++) acc[i][j] = 0.f;

#define ISSUE_PROJ(buf, k0)                                                  \
    do {                                                                     \
        _Pragma("unroll")                                                    \
        for (int i = 0; i < 2; i++) {                                        \
            int idx = t + 256 * i;                                           \
            int krow = idx >> 4, seg = idx & 15;                             \
            int nn = n0 + seg * 8;                                           \
            if (nn > NN - 8) nn = NN - 8;                                    \
            cpa16(smem_u32(&Ah[buf][krow][seg * 8]),                         \
                  vbase + (size_t)((k0) + krow) * NN + nn);                  \
            int erow = idx >> 2, bseg = idx & 3;                             \
            cpa16(smem_u32(&Bh[buf][erow][bseg * 8]),                        \
                  w2base + (size_t)(e0 + erow) * DD + (k0) + bseg * 8);      \
        }                                                                    \
    } while (0)

    ISSUE_PROJ(0, 0);
    CPA_COMMIT();

    // ldmatrix lane mapping: krow = kb + ((lane>>4)&1)*8 + (lane&7),
    //                        ncol = mwarp + ((lane>>3)&1)*8
    const int lgi = lane & 7;
    const int lk8 = ((lane >> 4) & 1) * 8;
    const int lm8 = ((lane >> 3) & 1) * 8;

    for (int ch = 0; ch < 12; ch++) {
        const int buf = ch & 1;
        if (ch < 11) {
            ISSUE_PROJ(buf ^ 1, (ch + 1) * 32);
            CPA_COMMIT();
            CPA_WAIT1();
        } else {
            CPA_WAIT0();
        }
        __syncthreads();
#pragma unroll
        for (int kk = 0; kk < 2; kk++) {
            const int kb = kk * 16;
            unsigned a[4][4], b[4][2];
#pragma unroll
            for (int mi = 0; mi < 4; mi++) {
                int m = wm * 64 + mi * 16;
                ldsm4t(a[mi], smem_u32(&Ah[buf][kb + lk8 + lgi][m + lm8]));
            }
#pragma unroll
            for (int ni = 0; ni < 4; ni++) {
                int e = wn * 32 + ni * 8 + g;
                b[ni][0] = *(const uint32_t*)&Bh[buf][e][kb + 2 * tg];
                b[ni][1] = *(const uint32_t*)&Bh[buf][e][kb + 8 + 2 * tg];
            }
#pragma unroll
            for (int mi = 0; mi < 4; mi++)
#pragma unroll
                for (int ni = 0; ni < 4; ni++)
                    mma_f16(acc[mi * 4 + ni], a[mi], b[ni]);
        }
        __syncthreads();
    }
#undef ISSUE_PROJ

    // Epilogue: stage [mL][e] slabs, store e-contiguous + bias (mask n >= NN)
    float (*Cs)[132] = (float (*)[132])ds;   // 32 x 132
#pragma unroll 1
    for (int slab = 0; slab < 4; slab++) {
        if ((slab >> 1) == wm) {
#pragma unroll
            for (int mi2 = 0; mi2 < 2; mi2++) {
                int mi = (slab & 1) * 2 + mi2;
#pragma unroll
                for (int ni = 0; ni < 4; ni++) {
                    int mL = mi2 * 16 + g;
                    int e = wn * 32 + ni * 8 + 2 * tg;
                    float* a4 = acc[mi * 4 + ni];
                    Cs[mL][e]         = a4[0];
                    Cs[mL][e + 1]     = a4[1];
                    Cs[mL + 8][e]     = a4[2];
                    Cs[mL + 8][e + 1] = a4[3];
                }
            }
        }
        __syncthreads();
#pragma unroll
        for (int it = 0; it < 4; it++) {
            int idx = t + 256 * it;
            int mL = idx >> 5, f = idx & 31;
            int n = n0 + slab * 32 + mL;
            if (n < NN) {
                float4 v = *(float4*)&Cs[mL][4 * f];
                float4 bi = *(const float4*)(bias + e0 + 4 * f);
                v.x += bi.x; v.y += bi.y; v.z += bi.z; v.w += bi.w;
                *(float4*)(out + ((size_t)b_ * NN + n) * DD + e0 + 4 * f) = v;
            }
        }
        __syncthreads();
    }
}

// ---------------------------------------------------------------------------
#define SMEM_QKV (2 * 128 * 40 * 2 * 2)                    // 40960 B (fp16)
#define SMEM_PROJ (2 * 32 * 136 * 2 + 2 * 128 * 40 * 2)    // 37888 B (fp16)

extern "C" void kernel_launch(void* const* d_in, const int* in_sizes, int n_in,
                              void* d_out, int out_size) {
    const float* x      = (const float*)d_in[0];
    const float* qkv_w  = (const float*)d_in[1];
    const float* temp   = (const float*)d_in[2];
    const float* proj_w = (const float*)d_in[3];
    const float* proj_b = (const float*)d_in[4];
    float* out = (float*)d_out;

    static int configured = 0;
    if (!configured) {
        cudaFuncSetAttribute(k_qkv,  cudaFuncAttributeMaxDynamicSharedMemorySize, SMEM_QKV);
        cudaFuncSetAttribute(k_proj, cudaFuncAttributeMaxDynamicSharedMemorySize, SMEM_PROJ);
        configured = 1;
    }

    k_cvt<<<4096, 256>>>(x, qkv_w);
    k_qkv<<<dim3(E3 / 128, ROWS / 128), 256, SMEM_QKV>>>();
    k_qk<<<dim3(BH, NSPLIT), 256>>>();
    k_softmax<<<BH, 64>>>(temp);
    k_wprime<<<dim3(BH, 3), 256>>>(proj_w);
    k_proj<<<dim3(DD / 128, (NN + 127) / 128, BB), 256, SMEM_PROJ>>>(proj_b, out);
}

// round 15
// speedup vs baseline: 1.5445x; 1.0178x over previous
#include <cuda_runtime.h>
#include <cuda_fp16.h>
#include <math.h>
#include <stdint.h>

#define BB 32
#define NN 3136
#define DD 384
#define HH 8
#define CC 48
#define BH 256          // BB*HH
#define ROWS 100352     // BB*NN
#define E3 1152         // 3*DD
#define NSPLIT 7
#define NCHUNK 448      // NN / NSPLIT

// Scratch (sanctioned __device__ globals; no allocations anywhere)
__device__ __half g_qkh[(size_t)2 * BH * CC * NN];  // q,k fp16 [2][bh][c][n]
__device__ __half g_vh[(size_t)BH * CC * NN];       // v fp16 [bh][c][n]
__device__ __half g_xh[(size_t)ROWS * DD];          // fp16-rounded x
__device__ __half g_wh[(size_t)E3 * DD];            // fp16-rounded qkv_w
__device__ float g_npart[(size_t)NSPLIT * BH * 96]; // sumsq partials (q rows, k rows)
__device__ float g_spart[(size_t)NSPLIT * BH * CC * CC];
__device__ float g_p[(size_t)BH * CC * CC];         // softmaxed attn
__device__ __half g_w2h[(size_t)BB * DD * DD];      // fused P@W weights fp16 [b][e][k]

// ---------------------------------------------------------------------------
// helpers
// ---------------------------------------------------------------------------
__device__ __forceinline__ uint32_t smem_u32(const void* p) {
    uint32_t a;
    asm("{ .reg .u64 t; cvta.to.shared.u64 t, %1; cvt.u32.u64 %0, t; }"
        : "=r"(a) : "l"(p));
    return a;
}
__device__ __forceinline__ void mma_f16(float* c, const unsigned* a,
                                        const unsigned* b) {
    asm volatile(
        "mma.sync.aligned.m16n8k16.row.col.f32.f16.f16.f32 "
        "{%0,%1,%2,%3}, {%4,%5,%6,%7}, {%8,%9}, {%0,%1,%2,%3};\n"
        : "+f"(c[0]), "+f"(c[1]), "+f"(c[2]), "+f"(c[3])
        : "r"(a[0]), "r"(a[1]), "r"(a[2]), "r"(a[3]), "r"(b[0]), "r"(b[1]));
}
__device__ __forceinline__ void ldsm4t(unsigned* r, uint32_t addr) {
    asm volatile(
        "ldmatrix.sync.aligned.m8n8.x4.trans.shared.b16 {%0,%1,%2,%3}, [%4];"
        : "=r"(r[0]), "=r"(r[1]), "=r"(r[2]), "=r"(r[3]) : "r"(addr));
}
__device__ __forceinline__ void cpa16(uint32_t s, const void* g) {
    asm volatile("cp.async.ca.shared.global [%0], [%1], 16;"
                 :: "r"(s), "l"(g) : "memory");
}
#define CPA_COMMIT() asm volatile("cp.async.commit_group;" ::: "memory")
#define CPA_WAIT1()  asm volatile("cp.async.wait_group 1;" ::: "memory")
#define CPA_WAIT0()  asm volatile("cp.async.wait_group 0;" ::: "memory")

// ---------------------------------------------------------------------------
// K0: round x and qkv_w to fp16 (rn) — feeds the fp16 qkv GEMM
// ---------------------------------------------------------------------------
__global__ __launch_bounds__(256) void k_cvt(const float* __restrict__ x,
                                             const float* __restrict__ w) {
    const size_t NX4 = (size_t)ROWS * DD / 4;
    const size_t NW4 = (size_t)E3 * DD / 4;
    for (size_t i = (size_t)blockIdx.x * 256 + threadIdx.x; i < NX4 + NW4;
         i += (size_t)gridDim.x * 256) {
        const float4 v = (i < NX4) ? ((const float4*)x)[i]
                                   : ((const float4*)w)[i - NX4];
        __half2 h0 = __floats2half2_rn(v.x, v.y);
        __half2 h1 = __floats2half2_rn(v.z, v.w);
        uint2 pk = make_uint2(*(uint32_t*)&h0, *(uint32_t*)&h1);
        if (i < NX4) ((uint2*)g_xh)[i] = pk;
        else         ((uint2*)g_wh)[i - NX4] = pk;
    }
}

// ---------------------------------------------------------------------------
// K1: qkv = xh @ wh^T via fp16 m16n8k16 MMA + cp.async double buffering.
// 128x128 tile, 12 K-chunks of 32; fp16 tiles, rows padded to 40 halfs.
// q,k,v all stored fp16 (q,k -> g_qkh; v -> g_vh), n-contiguous scatter.
// ---------------------------------------------------------------------------
__global__ __launch_bounds__(256) void k_qkv() {
    extern __shared__ __align__(16) unsigned char dsraw[];
    __half (*As)[128][40] = (__half (*)[128][40])dsraw;
    __half (*Bs)[128][40] = (__half (*)[128][40])(dsraw + 2 * 128 * 40 * 2);
    float* ds = (float*)dsraw;
    const int m0 = blockIdx.y * 128, e0 = blockIdx.x * 128;
    const int t = threadIdx.x, lane = t & 31, wid = t >> 5;
    const int wm = wid >> 2, wn = wid & 3;
    const int g = lane >> 2, tg = lane & 3;

    const int lrow0 = t >> 2, lseg0 = t & 3;
    const int lrow1 = (t + 256) >> 2, lseg1 = (t + 256) & 3;
    const __half* gx0 = g_xh + (size_t)(m0 + lrow0) * DD + lseg0 * 8;
    const __half* gx1 = g_xh + (size_t)(m0 + lrow1) * DD + lseg1 * 8;
    const __half* gw0 = g_wh + (size_t)(e0 + lrow0) * DD + lseg0 * 8;
    const __half* gw1 = g_wh + (size_t)(e0 + lrow1) * DD + lseg1 * 8;

    float acc[16][4];
#pragma unroll
    for (int i = 0; i < 16; i++)
#pragma unroll
        for (int j = 0; j < 4; j++) acc[i][j] = 0.f;

#define ISSUE_QKV(buf, k0)                                                   \
    do {                                                                     \
        cpa16(smem_u32(&As[buf][lrow0][lseg0 * 8]), gx0 + (k0));             \
        cpa16(smem_u32(&As[buf][lrow1][lseg1 * 8]), gx1 + (k0));             \
        cpa16(smem_u32(&Bs[buf][lrow0][lseg0 * 8]), gw0 + (k0));             \
        cpa16(smem_u32(&Bs[buf][lrow1][lseg1 * 8]), gw1 + (k0));             \
    } while (0)

    ISSUE_QKV(0, 0);
    CPA_COMMIT();

    for (int ch = 0; ch < 12; ch++) {
        const int buf = ch & 1;
        if (ch < 11) {
            ISSUE_QKV(buf ^ 1, (ch + 1) * 32);
            CPA_COMMIT();
            CPA_WAIT1();
        } else {
            CPA_WAIT0();
        }
        __syncthreads();
#pragma unroll
        for (int kk = 0; kk < 2; kk++) {
            const int kb = kk * 16 + 2 * tg;
            unsigned a[4][4], b[4][2];
#pragma unroll
            for (int mi = 0; mi < 4; mi++) {
                int m = wm * 64 + mi * 16 + g;
                a[mi][0] = *(const uint32_t*)&As[buf][m][kb];
                a[mi][1] = *(const uint32_t*)&As[buf][m + 8][kb];
                a[mi][2] = *(const uint32_t*)&As[buf][m][kb + 8];
                a[mi][3] = *(const uint32_t*)&As[buf][m + 8][kb + 8];
            }
#pragma unroll
            for (int ni = 0; ni < 4; ni++) {
                int e = wn * 32 + ni * 8 + g;
                b[ni][0] = *(const uint32_t*)&Bs[buf][e][kb];
                b[ni][1] = *(const uint32_t*)&Bs[buf][e][kb + 8];
            }
#pragma unroll
            for (int mi = 0; mi < 4; mi++)
#pragma unroll
                for (int ni = 0; ni < 4; ni++)
                    mma_f16(acc[mi * 4 + ni], a[mi], b[ni]);
        }
        __syncthreads();
    }
#undef ISSUE_QKV

    // Epilogue: stage [eL][m] slabs in smem; all outputs stored fp16
    float (*Cs)[132] = (float (*)[132])ds;   // 32 x 132
#pragma unroll 1
    for (int slab = 0; slab < 4; slab++) {
        if (wn == slab) {
#pragma unroll
            for (int mi = 0; mi < 4; mi++)
#pragma unroll
                for (int ni = 0; ni < 4; ni++) {
                    int eL = ni * 8 + 2 * tg;
                    int m = wm * 64 + mi * 16 + g;
                    float* a4 = acc[mi * 4 + ni];
                    Cs[eL][m]         = a4[0];
                    Cs[eL + 1][m]     = a4[1];
                    Cs[eL][m + 8]     = a4[2];
                    Cs[eL + 1][m + 8] = a4[3];
                }
        }
        __syncthreads();
#pragma unroll
        for (int it = 0; it < 4; it++) {
            int idx = t + 256 * it;          // 0..1023
            int eL = idx >> 5, f = idx & 31;
            int e = e0 + slab * 32 + eL;
            int s = e / DD;
            int rem = e - s * DD;
            int h = rem / CC;
            int c = rem - h * CC;
            int m = m0 + 4 * f;
            int b_ = m / NN;
            int n = m - b_ * NN;
            float4 vv = *(float4*)&Cs[eL][4 * f];
            __half2 h0 = __floats2half2_rn(vv.x, vv.y);
            __half2 h1 = __floats2half2_rn(vv.z, vv.w);
            uint2 pk = make_uint2(*(uint32_t*)&h0, *(uint32_t*)&h1);
            __half* dst = (s == 2)
                ? g_vh + ((size_t)(b_ * HH + h) * CC + c) * NN + n
                : g_qkh + ((size_t)((s * BB + b_) * HH + h) * CC + c) * NN + n;
            *(uint2*)dst = pk;
        }
        __syncthreads();
    }
}

// ---------------------------------------------------------------------------
// K3a: partial S[c][d] = sum_n q[c][n] k[d][n] over an n-chunk (scalar FMA,
// R13-proven structure) — now reading fp16 q,k and converting at load.
// Fused per-row sumsq partials on threads 0..95.
// ---------------------------------------------------------------------------
__global__ __launch_bounds__(256) void k_qk() {
    __shared__ float qs[48][68];
    __shared__ float ks[48][68];
    const int bh = blockIdx.x;
    const int n0 = blockIdx.y * NCHUNK;
    const int t  = threadIdx.x;
    const int ci = t >> 4, dj = t & 15;

    const __half* qb = g_qkh + (size_t)bh * CC * NN;
    const __half* kb = g_qkh + (size_t)(BH + bh) * CC * NN;

    float acc[3][3] = {};
    float nacc = 0.f;
    for (int cc = 0; cc < NCHUNK; cc += 64) {
        int nb = n0 + cc;
#pragma unroll
        for (int jj = 0; jj < 3; jj++) {
            int idx = t + 256 * jj;
            int c = idx >> 4, f = idx & 15;
            uint2 rq = *(const uint2*)(qb + (size_t)c * NN + nb + 4 * f);
            uint2 rk = *(const uint2*)(kb + (size_t)c * NN + nb + 4 * f);
            float2 q0 = __half22float2(*(__half2*)&rq.x);
            float2 q1 = __half22float2(*(__half2*)&rq.y);
            float2 k0 = __half22float2(*(__half2*)&rk.x);
            float2 k1 = __half22float2(*(__half2*)&rk.y);
            *(float4*)&qs[c][4 * f] = make_float4(q0.x, q0.y, q1.x, q1.y);
            *(float4*)&ks[c][4 * f] = make_float4(k0.x, k0.y, k1.x, k1.y);
        }
        __syncthreads();
        if (t < 96) {
            const float4* rowp = (t < 48) ? (const float4*)&qs[t][0]
                                          : (const float4*)&ks[t - 48][0];
#pragma unroll
            for (int f = 0; f < 16; f++) {
                float4 v = rowp[f];
                nacc += v.x * v.x + v.y * v.y + v.z * v.z + v.w * v.w;
            }
        }
#pragma unroll 8
        for (int nn = 0; nn < 64; nn++) {
            float a0 = qs[3 * ci + 0][nn];
            float a1 = qs[3 * ci + 1][nn];
            float a2 = qs[3 * ci + 2][nn];
            float b0 = ks[3 * dj + 0][nn];
            float b1 = ks[3 * dj + 1][nn];
            float b2 = ks[3 * dj + 2][nn];
            acc[0][0] += a0 * b0; acc[0][1] += a0 * b1; acc[0][2] += a0 * b2;
            acc[1][0] += a1 * b0; acc[1][1] += a1 * b1; acc[1][2] += a1 * b2;
            acc[2][0] += a2 * b0; acc[2][1] += a2 * b1; acc[2][2] += a2 * b2;
        }
        __syncthreads();
    }
    float* out = g_spart + ((size_t)blockIdx.y * BH + bh) * (CC * CC);
#pragma unroll
    for (int i = 0; i < 3; i++)
#pragma unroll
        for (int j = 0; j < 3; j++)
            out[(3 * ci + i) * CC + (3 * dj + j)] = acc[i][j];
    if (t < 96)
        g_npart[((size_t)blockIdx.y * BH + bh) * 96 + t] = nacc;
}

// ---------------------------------------------------------------------------
// K3b: reduce partials (S and norms), scale, row softmax -> g_p
// ---------------------------------------------------------------------------
__global__ __launch_bounds__(64) void k_softmax(const float* __restrict__ temp) {
    __shared__ float S[48][48];
    __shared__ float inorm[96];
    const int bh = blockIdx.x;
    const int t  = threadIdx.x;
    const float tp = temp[bh % HH];
    for (int r = t; r < 96; r += 64) {
        float s = 0.f;
#pragma unroll
        for (int p = 0; p < NSPLIT; p++)
            s += g_npart[((size_t)p * BH + bh) * 96 + r];
        inorm[r] = 1.f / fmaxf(sqrtf(s), 1e-12f);
    }
    __syncthreads();
    for (int idx = t; idx < CC * CC; idx += 64) {
        float s = 0.f;
#pragma unroll
        for (int p = 0; p < NSPLIT; p++)
            s += g_spart[((size_t)p * BH + bh) * (CC * CC) + idx];
        int c = idx / CC, d = idx - c * CC;
        s *= inorm[c] * inorm[48 + d] * tp;
        S[c][d] = s;
    }
    __syncthreads();
    if (t < 48) {
        float mx = -1e30f;
#pragma unroll
        for (int d = 0; d < 48; d++) mx = fmaxf(mx, S[t][d]);
        float sum = 0.f;
#pragma unroll
        for (int d = 0; d < 48; d++) {
            float e = __expf(S[t][d] - mx);
            S[t][d] = e;
            sum += e;
        }
        float inv = 1.f / sum;
#pragma unroll
        for (int d = 0; d < 48; d++)
            g_p[(size_t)bh * (CC * CC) + t * CC + d] = S[t][d] * inv;
    }
}

// ---------------------------------------------------------------------------
// K_W2: W2[b][e][h*48+d] = sum_c P[b,h,c,d] * W[e][h*48+c]  -> fp16
// grid (BH, 3); 4 independent c-partials per output for ILP
// ---------------------------------------------------------------------------
__global__ __launch_bounds__(256) void k_wprime(const float* __restrict__ w) {
    __shared__ float Ps[48][49];   // [c][d]
    const int bh = blockIdx.x;
    const int b_ = bh / HH, h = bh % HH;
    const int eseg = blockIdx.y;   // 0..2, 128 e each
    const int t = threadIdx.x;
    for (int idx = t; idx < CC * CC; idx += 256) {
        int c = idx / CC;
        Ps[c][idx - c * CC] = g_p[(size_t)bh * (CC * CC) + idx];
    }
    __syncthreads();
    for (int idx = t; idx < 128 * CC; idx += 256) {
        int eL = idx / CC, d = idx - (idx / CC) * CC;
        int e = eseg * 128 + eL;
        const float* wr = w + (size_t)e * DD + h * CC;
        float s0 = 0.f, s1 = 0.f, s2 = 0.f, s3 = 0.f;
#pragma unroll
        for (int c = 0; c < CC; c += 4) {
            s0 += Ps[c + 0][d] * wr[c + 0];
            s1 += Ps[c + 1][d] * wr[c + 1];
            s2 += Ps[c + 2][d] * wr[c + 2];
            s3 += Ps[c + 3][d] * wr[c + 3];
        }
        g_w2h[((size_t)b_ * DD + e) * DD + h * CC + d] =
            __float2half_rn((s0 + s1) + (s2 + s3));
    }
}

// ---------------------------------------------------------------------------
// K5: final[b,n,e] = sum_k v[b][k][n] * W2[b][e][k] + bias  via fp16 MMA
// A (V) staged [k][n] fp16, loaded with ldmatrix.x4.trans; B (W2) [e][k] fp16.
// grid (3 e-tiles, 25 n-tiles, 32 b); 128x128 tile, K chunks of 32
// ---------------------------------------------------------------------------
__global__ __launch_bounds__(256) void k_proj(const float* __restrict__ bias,
                                              float* __restrict__ out) {
    extern __shared__ __align__(16) unsigned char dsraw[];
    __half (*Ah)[32][136] = (__half (*)[32][136])dsraw;            // [k][n]
    __half (*Bh)[128][40] = (__half (*)[128][40])(dsraw + 2 * 32 * 136 * 2);
    float* ds = (float*)dsraw;
    const int n0 = blockIdx.y * 128, e0 = blockIdx.x * 128;
    const int b_ = blockIdx.z;
    const int t = threadIdx.x, lane = t & 31, wid = t >> 5;
    const int wm = wid >> 2, wn = wid & 3;
    const int g = lane >> 2, tg = lane & 3;

    const __half* vbase = g_vh + (size_t)(b_ * HH) * CC * NN;
    const __half* w2base = g_w2h + (size_t)b_ * DD * DD;

    float acc[16][4];
#pragma unroll
    for (int i = 0; i < 16; i++)
#pragma unroll
        for (int j = 0; j < 4; j++) acc[i][j] = 0.f;

#define ISSUE_PROJ(buf, k0)                                                  \
    do {                                                                     \
        _Pragma("unroll")                                                    \
        for (int i = 0; i < 2; i++) {                                        \
            int idx = t + 256 * i;                                           \
            int krow = idx >> 4, seg = idx & 15;                             \
            int nn = n0 + seg * 8;                                           \
            if (nn > NN - 8) nn = NN - 8;                                    \
            cpa16(smem_u32(&Ah[buf][krow][seg * 8]),                         \
                  vbase + (size_t)((k0) + krow) * NN + nn);                  \
            int erow = idx >> 2, bseg = idx & 3;                             \
            cpa16(smem_u32(&Bh[buf][erow][bseg * 8]),                        \
                  w2base + (size_t)(e0 + erow) * DD + (k0) + bseg * 8);      \
        }                                                                    \
    } while (0)

    ISSUE_PROJ(0, 0);
    CPA_COMMIT();

    const int lgi = lane & 7;
    const int lk8 = ((lane >> 4) & 1) * 8;
    const int lm8 = ((lane >> 3) & 1) * 8;

    for (int ch = 0; ch < 12; ch++) {
        const int buf = ch & 1;
        if (ch < 11) {
            ISSUE_PROJ(buf ^ 1, (ch + 1) * 32);
            CPA_COMMIT();
            CPA_WAIT1();
        } else {
            CPA_WAIT0();
        }
        __syncthreads();
#pragma unroll
        for (int kk = 0; kk < 2; kk++) {
            const int kb = kk * 16;
            unsigned a[4][4], b[4][2];
#pragma unroll
            for (int mi = 0; mi < 4; mi++) {
                int m = wm * 64 + mi * 16;
                ldsm4t(a[mi], smem_u32(&Ah[buf][kb + lk8 + lgi][m + lm8]));
            }
#pragma unroll
            for (int ni = 0; ni < 4; ni++) {
                int e = wn * 32 + ni * 8 + g;
                b[ni][0] = *(const uint32_t*)&Bh[buf][e][kb + 2 * tg];
                b[ni][1] = *(const uint32_t*)&Bh[buf][e][kb + 8 + 2 * tg];
            }
#pragma unroll
            for (int mi = 0; mi < 4; mi++)
#pragma unroll
                for (int ni = 0; ni < 4; ni++)
                    mma_f16(acc[mi * 4 + ni], a[mi], b[ni]);
        }
        __syncthreads();
    }
#undef ISSUE_PROJ

    // Epilogue: stage [mL][e] slabs, store e-contiguous + bias (mask n >= NN)
    float (*Cs)[132] = (float (*)[132])ds;   // 32 x 132
#pragma unroll 1
    for (int slab = 0; slab < 4; slab++) {
        if ((slab >> 1) == wm) {
#pragma unroll
            for (int mi2 = 0; mi2 < 2; mi2++) {
                int mi = (slab & 1) * 2 + mi2;
#pragma unroll
                for (int ni = 0; ni < 4; ni++) {
                    int mL = mi2 * 16 + g;
                    int e = wn * 32 + ni * 8 + 2 * tg;
                    float* a4 = acc[mi * 4 + ni];
                    Cs[mL][e]         = a4[0];
                    Cs[mL][e + 1]     = a4[1];
                    Cs[mL + 8][e]     = a4[2];
                    Cs[mL + 8][e + 1] = a4[3];
                }
            }
        }
        __syncthreads();
#pragma unroll
        for (int it = 0; it < 4; it++) {
            int idx = t + 256 * it;
            int mL = idx >> 5, f = idx & 31;
            int n = n0 + slab * 32 + mL;
            if (n < NN) {
                float4 v = *(float4*)&Cs[mL][4 * f];
                float4 bi = *(const float4*)(bias + e0 + 4 * f);
                v.x += bi.x; v.y += bi.y; v.z += bi.z; v.w += bi.w;
                *(float4*)(out + ((size_t)b_ * NN + n) * DD + e0 + 4 * f) = v;
            }
        }
        __syncthreads();
    }
}

// ---------------------------------------------------------------------------
#define SMEM_QKV (2 * 128 * 40 * 2 * 2)                    // 40960 B (fp16)
#define SMEM_PROJ (2 * 32 * 136 * 2 + 2 * 128 * 40 * 2)    // 37888 B (fp16)

extern "C" void kernel_launch(void* const* d_in, const int* in_sizes, int n_in,
                              void* d_out, int out_size) {
    const float* x      = (const float*)d_in[0];
    const float* qkv_w  = (const float*)d_in[1];
    const float* temp   = (const float*)d_in[2];
    const float* proj_w = (const float*)d_in[3];
    const float* proj_b = (const float*)d_in[4];
    float* out = (float*)d_out;

    static int configured = 0;
    if (!configured) {
        cudaFuncSetAttribute(k_qkv,  cudaFuncAttributeMaxDynamicSharedMemorySize, SMEM_QKV);
        cudaFuncSetAttribute(k_proj, cudaFuncAttributeMaxDynamicSharedMemorySize, SMEM_PROJ);
        configured = 1;
    }

    k_cvt<<<4096, 256>>>(x, qkv_w);
    k_qkv<<<dim3(E3 / 128, ROWS / 128), 256, SMEM_QKV>>>();
    k_qk<<<dim3(BH, NSPLIT), 256>>>();
    k_softmax<<<BH, 64>>>(temp);
    k_wprime<<<dim3(BH, 3), 256>>>(proj_w);
    k_proj<<<dim3(DD / 128, (NN + 127) / 128, BB), 256, SMEM_PROJ>>>(proj_b, out);
}